// round 5
// baseline (speedup 1.0000x reference)
#include <cuda_runtime.h>

// SpikeLoss: loss = 0.5 * sum( (outputs - psp(target))^2 )
// psp: syn_t = syn_{t-1}*0.8 + x_t ; y_t = syn_t * 0.2
// [B=32,C=256,H=4,W=4,T=100], T contiguous -> 131072 rows of 100 floats.
//
// Per CTA (128 threads = 128 rows, 2 syncs total):
//   P1: coalesced float4 load of target tile -> smem (pitch 101)
//   P2: per-thread in-place scan, smem := psp(target)   (conflict-free)
//   P3: coalesced float4 loads of outputs (never staged), diff vs smem y
//   Fused deterministic last-block reduction (single kernel launch).

#define T_STEPS   100
#define DECAY     0.8f
#define INV_TAU   0.2f

#define THREADS   128
#define ROWS_PB   128
#define F4_ROW    (T_STEPS / 4)            // 25 float4 per row
#define PITCH     101                      // odd -> conflict-free scan
#define SMEM_BYTES (ROWS_PB * PITCH * 4)   // 51712
#define NBLOCKS   1024                     // 131072 / 128

__device__ float    g_partials[NBLOCKS];
__device__ unsigned g_count = 0;

__global__ void __launch_bounds__(THREADS)
spike_loss_fused(const float* __restrict__ outputs,
                 const float* __restrict__ target,
                 float* __restrict__ out,
                 int n_blocks)
{
    extern __shared__ float s[];
    __shared__ float s_warp[THREADS / 32];
    __shared__ int   s_is_last;

    const int tid = threadIdx.x;
    const size_t base4 = (size_t)blockIdx.x * (ROWS_PB * F4_ROW);
    const float4* __restrict__ gt = (const float4*)target  + base4;
    const float4* __restrict__ go = (const float4*)outputs + base4;

    // ---- Phase 1: coalesced target -> smem  (note: r*25+c == i) ----
    #pragma unroll
    for (int k = 0; k < F4_ROW; k++) {
        int i = tid + k * THREADS;
        float4 v = __ldcs(&gt[i]);
        int r = i / F4_ROW;
        int c = i - r * F4_ROW;
        float* d = s + r * PITCH + 4 * c;
        d[0] = v.x; d[1] = v.y; d[2] = v.z; d[3] = v.w;
    }
    __syncthreads();

    // ---- Phase 2: in-place scan of own row (bank-conflict-free) ----
    {
        float syn = 0.0f;
        float* row = s + tid * PITCH;
        #pragma unroll
        for (int t = 0; t < T_STEPS; t++) {
            syn = syn * DECAY + row[t];
            row[t] = syn * INV_TAU;
        }
    }
    __syncthreads();

    // ---- Phase 3: coalesced outputs loads, diff against smem psp ----
    float acc = 0.0f;
    #pragma unroll
    for (int k = 0; k < F4_ROW; k++) {
        int i = tid + k * THREADS;
        float4 o = __ldcs(&go[i]);
        int r = i / F4_ROW;
        int c = i - r * F4_ROW;
        const float* y = s + r * PITCH + 4 * c;
        float d0 = o.x - y[0];
        float d1 = o.y - y[1];
        float d2 = o.z - y[2];
        float d3 = o.w - y[3];
        acc = fmaf(d0, d0, acc);
        acc = fmaf(d1, d1, acc);
        acc = fmaf(d2, d2, acc);
        acc = fmaf(d3, d3, acc);
    }

    // ---- Block reduction ----
    #pragma unroll
    for (int off = 16; off > 0; off >>= 1)
        acc += __shfl_down_sync(0xFFFFFFFFu, acc, off);

    int lane = tid & 31, wid = tid >> 5;
    if (lane == 0) s_warp[wid] = acc;
    __syncthreads();
    if (tid == 0) {
        float v = s_warp[0] + s_warp[1] + s_warp[2] + s_warp[3];
        g_partials[blockIdx.x] = v;
        __threadfence();
        unsigned old = atomicAdd(&g_count, 1u);
        s_is_last = (old == (unsigned)(n_blocks - 1));
    }
    __syncthreads();

    // ---- Last block: deterministic final reduce ----
    if (s_is_last) {
        float v = 0.0f;
        #pragma unroll
        for (int j = 0; j < NBLOCKS / THREADS; j++) {      // fixed order
            int idx = tid + j * THREADS;
            if (idx < n_blocks) v += g_partials[idx];
        }
        #pragma unroll
        for (int off = 16; off > 0; off >>= 1)
            v += __shfl_down_sync(0xFFFFFFFFu, v, off);
        if (lane == 0) s_warp[wid] = v;
        __syncthreads();
        if (tid == 0) {
            out[0] = 0.5f * (s_warp[0] + s_warp[1] + s_warp[2] + s_warp[3]);
            g_count = 0;   // reset for next graph replay
        }
    }
}

extern "C" void kernel_launch(void* const* d_in, const int* in_sizes, int n_in,
                              void* d_out, int out_size)
{
    const float* outputs = (const float*)d_in[0];
    const float* target  = (const float*)d_in[1];
    float* out = (float*)d_out;

    int n_rows = in_sizes[0] / T_STEPS;     // 131072
    int blocks = n_rows / ROWS_PB;          // 1024

    cudaFuncSetAttribute(spike_loss_fused,
                         cudaFuncAttributeMaxDynamicSharedMemorySize,
                         SMEM_BYTES);

    spike_loss_fused<<<blocks, THREADS, SMEM_BYTES>>>(outputs, target, out, blocks);
}

// round 6
// speedup vs baseline: 2.0336x; 2.0336x over previous
#include <cuda_runtime.h>

// SpikeLoss: loss = 0.5 * sum( (outputs - psp(target))^2 )
// psp: syn_t = 0.8*syn_{t-1} + x_t ; y_t = 0.2*syn_t
// [32,256,4,4,100], T contiguous -> 131072 rows of 100 floats.
//
// One WARP per row. Lane l holds timesteps [4l,4l+3] via one float4 load
// (lanes 0..24 active; fully coalesced, 400B contiguous per row).
// Linear recurrence parallelized: intra-lane 4-step scan, then 5-step
// Kogge-Stone over segment totals (ratio 0.8^4), exclusive carry,
// reconstruct. No shared memory, no barriers in the hot path.
// Fused deterministic last-block-done final reduction (single launch).

#define T_STEPS   100
#define THREADS   256
#define WARPS_PB  (THREADS / 32)        // 8
#define NBLOCKS   1024
#define ROWS_PER_WARP 16                // 131072 / (1024*8)

#define A1  0.8f
#define A2  0.64f
#define A3  0.512f
#define A4  0.4096f
#define A8  0.16777216f
#define A16 0.028147497671065608f
#define A32 0.0007922816251426434f
#define A64 6.277101735386681e-07f
#define INV_TAU 0.2f

__device__ float    g_partials[NBLOCKS];
__device__ unsigned g_count = 0;

__global__ void __launch_bounds__(THREADS)
spike_loss_warpscan(const float* __restrict__ outputs,
                    const float* __restrict__ target,
                    float* __restrict__ out,
                    int n_blocks)
{
    __shared__ float s_warp[WARPS_PB];
    __shared__ int   s_is_last;

    const int tid  = threadIdx.x;
    const int lane = tid & 31;
    const int wid  = tid >> 5;
    const int gwarp = blockIdx.x * WARPS_PB + wid;
    const bool active = (lane < 25);

    const float4* __restrict__ t4 = (const float4*)target;
    const float4* __restrict__ o4 = (const float4*)outputs;

    float acc = 0.0f;

    #pragma unroll 2
    for (int i = 0; i < ROWS_PER_WARP; i++) {
        const size_t row  = (size_t)gwarp * ROWS_PER_WARP + i;
        const size_t base = row * 25;

        float4 x = make_float4(0.f, 0.f, 0.f, 0.f);
        float4 o = make_float4(0.f, 0.f, 0.f, 0.f);
        if (active) {
            x = __ldcs(&t4[base + lane]);
            o = __ldcs(&o4[base + lane]);
        }

        // Intra-lane scan of 4 timesteps
        float p0 = x.x;
        float p1 = fmaf(A1, p0, x.y);
        float p2 = fmaf(A1, p1, x.z);
        float p3 = fmaf(A1, p2, x.w);

        // Kogge-Stone inclusive scan over segment totals (ratio 0.8^4)
        float T = p3, u;
        u = __shfl_up_sync(0xFFFFFFFFu, T, 1);  if (lane >= 1)  T = fmaf(A4,  u, T);
        u = __shfl_up_sync(0xFFFFFFFFu, T, 2);  if (lane >= 2)  T = fmaf(A8,  u, T);
        u = __shfl_up_sync(0xFFFFFFFFu, T, 4);  if (lane >= 4)  T = fmaf(A16, u, T);
        u = __shfl_up_sync(0xFFFFFFFFu, T, 8);  if (lane >= 8)  T = fmaf(A32, u, T);
        u = __shfl_up_sync(0xFFFFFFFFu, T, 16); if (lane >= 16) T = fmaf(A64, u, T);

        // Exclusive carry: syn entering this lane's segment
        float C = __shfl_up_sync(0xFFFFFFFFu, T, 1);
        if (lane == 0) C = 0.0f;

        // Reconstruct syn, diff against outputs, accumulate
        float s0 = fmaf(A1, C, p0);
        float s1 = fmaf(A2, C, p1);
        float s2 = fmaf(A3, C, p2);
        float s3 = fmaf(A4, C, p3);

        if (active) {
            float d0 = fmaf(-INV_TAU, s0, o.x);
            float d1 = fmaf(-INV_TAU, s1, o.y);
            float d2 = fmaf(-INV_TAU, s2, o.z);
            float d3 = fmaf(-INV_TAU, s3, o.w);
            acc = fmaf(d0, d0, acc);
            acc = fmaf(d1, d1, acc);
            acc = fmaf(d2, d2, acc);
            acc = fmaf(d3, d3, acc);
        }
    }

    // ---- Block reduction (deterministic) ----
    #pragma unroll
    for (int off = 16; off > 0; off >>= 1)
        acc += __shfl_down_sync(0xFFFFFFFFu, acc, off);
    if (lane == 0) s_warp[wid] = acc;
    __syncthreads();

    if (tid == 0) {
        float v = 0.0f;
        #pragma unroll
        for (int w = 0; w < WARPS_PB; w++) v += s_warp[w];
        g_partials[blockIdx.x] = v;
        __threadfence();
        unsigned old = atomicAdd(&g_count, 1u);
        s_is_last = (old == (unsigned)(n_blocks - 1));
    }
    __syncthreads();

    // ---- Last block: deterministic final reduce ----
    if (s_is_last) {
        float v = 0.0f;
        #pragma unroll
        for (int j = 0; j < NBLOCKS / THREADS; j++) {      // fixed order
            int idx = tid + j * THREADS;
            if (idx < n_blocks) v += g_partials[idx];
        }
        #pragma unroll
        for (int off = 16; off > 0; off >>= 1)
            v += __shfl_down_sync(0xFFFFFFFFu, v, off);
        if (lane == 0) s_warp[wid] = v;
        __syncthreads();
        if (tid == 0) {
            float r = 0.0f;
            #pragma unroll
            for (int w = 0; w < WARPS_PB; w++) r += s_warp[w];
            out[0] = 0.5f * r;
            g_count = 0;   // reset for next graph replay
        }
    }
}

extern "C" void kernel_launch(void* const* d_in, const int* in_sizes, int n_in,
                              void* d_out, int out_size)
{
    const float* outputs = (const float*)d_in[0];
    const float* target  = (const float*)d_in[1];
    float* out = (float*)d_out;

    int n_rows  = in_sizes[0] / T_STEPS;    // 131072
    int blocks  = n_rows / (WARPS_PB * ROWS_PER_WARP);  // 1024

    spike_loss_warpscan<<<blocks, THREADS>>>(outputs, target, out, blocks);
}